// round 15
// baseline (speedup 1.0000x reference)
#include <cuda_runtime.h>
#include <cuda_fp16.h>
#include <cstdint>
#include <mma.h>

using namespace nvcuda;

#define NEMBD 1024
#define TT 128
#define HS 128
#define NB 256

// W pre-converted to fp16 (device global; no allocations allowed).
__device__ __half g_wh[(size_t)3 * NEMBD * HS];    // Wq|Wk|Wv, RN fp16

// ---------------------------------------------------------------------------
// Pre-pass: RN-round W fp32 -> fp16.
// ---------------------------------------------------------------------------
__global__ void conv_wh_kernel(const float* __restrict__ wq,
                               const float* __restrict__ wk,
                               const float* __restrict__ wv)
{
    const int n4 = NEMBD * HS / 4;
    int stride = gridDim.x * blockDim.x;
    for (int i = blockIdx.x * blockDim.x + threadIdx.x; i < 3 * n4; i += stride) {
        int w = i / n4, j = i % n4;
        const float* src = (w == 0) ? wq : (w == 1) ? wk : wv;
        float4 v = reinterpret_cast<const float4*>(src)[j];
        reinterpret_cast<__half2*>(g_wh)[i * 2 + 0] = __floats2half2_rn(v.x, v.y);
        reinterpret_cast<__half2*>(g_wh)[i * 2 + 1] = __floats2half2_rn(v.z, v.w);
    }
}

// ---------------------------------------------------------------------------
// Fused kernel (R14 structure): per-batch QKV GEMM (fp16 HMMA) + RoPE +
// causal attention. 256 CTAs, 512 threads / 16 warps.
// Change vs R14: prefetch cp.async for stage it+3 is issued BEFORE the MMA
// loop (right after the barrier) so the loads overlap the ~24 MMAs instead
// of starting after them. Buffer (it+3)&3 was last read at iteration it-1,
// which completed before this iteration's barrier — safe.
// ---------------------------------------------------------------------------
static constexpr int A32_LD = 36;                      // floats (32 + 4 pad)
static constexpr int AH_LD  = 40;                      // halves (32 + 8 pad)
static constexpr int BH_LD  = 392;                     // halves (384 + 8 pad)
static constexpr int A32_B  = 128 * A32_LD * 4;        // 18432 B
static constexpr int AH_B   = 128 * AH_LD * 2;         // 10240 B
static constexpr int BH_B   = 32 * BH_LD * 2;          // 25088 B
static constexpr int STG_B  = A32_B + AH_B + BH_B;     // 53760 B
static constexpr int NBUF   = 4;
static constexpr int FUSED_SMEM = NBUF * STG_B;        // 215040 B

// Post-mainloop layout (within the same allocation):
static constexpr int SC_LD   = 132;                    // staging C / S, floats
static constexpr int SC_B    = 128 * SC_LD * 4;        // 67584 B
static constexpr int QK_LD   = 136;                    // fp16 tile ld (halves)
static constexpr int TILE_B  = 128 * QK_LD * 2;        // 34816 B
static constexpr int SQ_OFF  = SC_B;                   // 67584
static constexpr int SK_OFF  = SQ_OFF + TILE_B;        // 102400
static constexpr int SV_OFF  = SK_OFF + TILE_B;        // 137216  (end 172032)
static constexpr int SP_LD   = 264;                    // P halves ld

__device__ __forceinline__ void cp_async16(void* sptr, const void* gptr)
{
    uint32_t sa = (uint32_t)__cvta_generic_to_shared(sptr);
    asm volatile("cp.async.cg.shared.global [%0], [%1], 16;\n" :: "r"(sa), "l"(gptr));
}

__global__ void __launch_bounds__(512)
fused_head_kernel(const float* __restrict__ x, float* __restrict__ out)
{
    extern __shared__ char smemc[];
    const int b    = blockIdx.x;          // batch
    const int tid  = threadIdx.x;
    const int warp = tid >> 5;
    const int lane = tid & 31;
    const int wm   = warp >> 2;           // 0..3 -> 32-row band
    const int wn   = warp & 3;            // 0..3 -> 96-col band (phase 1)

    const float* xbase = x + (size_t)b * TT * NEMBD;

    // A chunk ownership (load AND convert): row cr, 8-float segment cc0.
    const int cr  = tid >> 2;
    const int cc0 = (tid & 3) * 8;

    // ============================ Phase 1: QKV GEMM ========================
    {
        wmma::fragment<wmma::accumulator, 16, 16, 16, float> acc[2][6];
        #pragma unroll
        for (int i = 0; i < 2; i++)
            #pragma unroll
            for (int j = 0; j < 6; j++)
                wmma::fill_fragment(acc[i][j], 0.0f);

        auto load_stage = [&](int stage) {      // stage 0..31
            char* st = smemc + (stage & 3) * STG_B;
            float*  As32 = reinterpret_cast<float*>(st);
            __half* Bs   = reinterpret_cast<__half*>(st + A32_B + AH_B);
            int k0 = stage * 32;
            // A: each thread loads ITS OWN 8 floats (2 x 16B).
            cp_async16(As32 + cr * A32_LD + cc0,
                       xbase + (size_t)cr * NEMBD + k0 + cc0);
            cp_async16(As32 + cr * A32_LD + cc0 + 4,
                       xbase + (size_t)cr * NEMBD + k0 + cc0 + 4);
            // B: 1536 8-half ops, 3/thread
            #pragma unroll
            for (int j = 0; j < 3; j++) {
                int idx = tid + j * 512;
                int r = idx / 48, c = idx % 48;
                int w = c >> 4;
                int cc = (c & 15) * 8;
                cp_async16(Bs + r * BH_LD + c * 8,
                           g_wh + (size_t)w * NEMBD * HS + (size_t)(k0 + r) * HS + cc);
            }
        };

        load_stage(0); asm volatile("cp.async.commit_group;\n");
        load_stage(1); asm volatile("cp.async.commit_group;\n");
        load_stage(2); asm volatile("cp.async.commit_group;\n");

        for (int it = 0; it < 32; ++it) {
            asm volatile("cp.async.wait_group 2;\n");

            char* st = smemc + (it & 3) * STG_B;
            float*  As32 = reinterpret_cast<float*>(st);
            __half* Ah   = reinterpret_cast<__half*>(st + A32_B);
            __half* Bs   = reinterpret_cast<__half*>(st + A32_B + AH_B);

            // Convert OWN chunk (visible after wait_group): 2xLDS.128 ->
            // 1xSTS.128. No barrier needed before this.
            {
                const float4* src = reinterpret_cast<const float4*>(As32 + cr * A32_LD + cc0);
                float4 f0 = src[0], f1 = src[1];
                uint4 o;
                reinterpret_cast<__half2*>(&o)[0] = __floats2half2_rn(f0.x, f0.y);
                reinterpret_cast<__half2*>(&o)[1] = __floats2half2_rn(f0.z, f0.w);
                reinterpret_cast<__half2*>(&o)[2] = __floats2half2_rn(f1.x, f1.y);
                reinterpret_cast<__half2*>(&o)[3] = __floats2half2_rn(f1.z, f1.w);
                *reinterpret_cast<uint4*>(Ah + cr * AH_LD + cc0) = o;
            }
            __syncthreads();     // publish Ah(it) + B(it); also fences buffer reuse

            // Prefetch stage it+3 NOW (overlaps the MMA loop below). Its
            // buffer (it+3)&3 == (it-1)&3 was fully consumed last iteration.
            if (it + 3 < 32) load_stage(it + 3);
            asm volatile("cp.async.commit_group;\n");

            #pragma unroll
            for (int kk = 0; kk < 32; kk += 16) {
                wmma::fragment<wmma::matrix_a, 16, 16, 16, __half, wmma::row_major> af[2];
                wmma::fragment<wmma::matrix_b, 16, 16, 16, __half, wmma::row_major> bf[6];
                #pragma unroll
                for (int i = 0; i < 2; i++)
                    wmma::load_matrix_sync(af[i], Ah + (wm * 32 + i * 16) * AH_LD + kk, AH_LD);
                #pragma unroll
                for (int j = 0; j < 6; j++)
                    wmma::load_matrix_sync(bf[j], Bs + kk * BH_LD + wn * 96 + j * 16, BH_LD);
                #pragma unroll
                for (int i = 0; i < 2; i++)
                    #pragma unroll
                    for (int j = 0; j < 6; j++)
                        wmma::mma_sync(acc[i][j], af[i], bf[j], acc[i][j]);
            }
        }

        asm volatile("cp.async.wait_group 0;\n");
        __syncthreads();

        // ---- Epilogue: q/k sections staged + RoPE; v stored directly ------
        float* stage = reinterpret_cast<float*>(smemc);               // [128][132]
        const float nlt = -logf(10000.0f) * (2.0f / 128.0f);

        #pragma unroll
        for (int w = 0; w < 2; w++) {           // q and k only
            #pragma unroll
            for (int i = 0; i < 2; i++)
                #pragma unroll
                for (int j = 0; j < 6; j++) {
                    int colg = wn * 96 + j * 16;
                    if (colg >= w * 128 && colg < w * 128 + 128)
                        wmma::store_matrix_sync(
                            stage + (wm * 32 + i * 16) * SC_LD + (colg - w * 128),
                            acc[i][j], SC_LD, wmma::mem_row_major);
                }
            __syncthreads();

            __half* tile = reinterpret_cast<__half*>(
                smemc + (w == 0 ? SQ_OFF : SK_OFF));
            const float qs = (w == 0) ? 0.08838834764831845f : 1.0f;  // 1/sqrt(128)

            for (int idx = tid; idx < 128 * 64; idx += 512) {   // (row, pair)
                int r = idx >> 6;
                int p = idx & 63;
                float crv = stage[r * SC_LD + 2 * p];
                float civ = stage[r * SC_LD + 2 * p + 1];
                float inv_freq = __expf(nlt * (float)p);
                float ang = (float)r * inv_freq;
                float s, c;
                sincosf(ang, &s, &c);
                float o0 = (crv * c - civ * s) * qs;
                float o1 = (crv * s + civ * c) * qs;
                reinterpret_cast<__half2*>(tile + r * QK_LD)[p] = __floats2half2_rn(o0, o1);
            }
            __syncthreads();
        }

        // v section (global cols [256,384)): direct half-fragment stores.
        {
            __half* sv = reinterpret_cast<__half*>(smemc + SV_OFF);
            #pragma unroll
            for (int i = 0; i < 2; i++)
                #pragma unroll
                for (int j = 0; j < 6; j++) {
                    int colg = wn * 96 + j * 16;
                    if (colg >= 256) {
                        wmma::fragment<wmma::accumulator, 16, 16, 16, __half> hf;
                        #pragma unroll
                        for (int e = 0; e < hf.num_elements; e++)
                            hf.x[e] = __float2half_rn(acc[i][j].x[e]);
                        wmma::store_matrix_sync(sv + (wm * 32 + i * 16) * QK_LD + (colg - 256),
                                                hf, QK_LD, wmma::mem_row_major);
                    }
                }
            __syncthreads();
        }
    }

    // ============================ Phase 2: attention ========================
    {
        __half* sq = reinterpret_cast<__half*>(smemc + SQ_OFF);
        __half* sk = reinterpret_cast<__half*>(smemc + SK_OFF);
        __half* sv = reinterpret_cast<__half*>(smemc + SV_OFF);
        float*  sS = reinterpret_cast<float*>(smemc);        // [128][132]
        __half* sp = reinterpret_cast<__half*>(smemc);       // P view, ld 264

        const int wm2 = warp >> 2;   // 0..3 -> 32-row band
        const int wn2 = warp & 3;    // 0..3 -> 32-col band

        // S = q @ k^T
        wmma::fragment<wmma::accumulator, 16, 16, 16, float> acc[2][2];
        #pragma unroll
        for (int i = 0; i < 2; i++)
            #pragma unroll
            for (int j = 0; j < 2; j++)
                wmma::fill_fragment(acc[i][j], 0.0f);

        #pragma unroll
        for (int kk = 0; kk < HS; kk += 16) {
            wmma::fragment<wmma::matrix_a, 16, 16, 16, __half, wmma::row_major> af[2];
            wmma::fragment<wmma::matrix_b, 16, 16, 16, __half, wmma::col_major> bf[2];
            #pragma unroll
            for (int i = 0; i < 2; i++)
                wmma::load_matrix_sync(af[i], sq + (wm2 * 32 + i * 16) * QK_LD + kk, QK_LD);
            #pragma unroll
            for (int j = 0; j < 2; j++)
                wmma::load_matrix_sync(bf[j], sk + (wn2 * 32 + j * 16) * QK_LD + kk, QK_LD);
            #pragma unroll
            for (int i = 0; i < 2; i++)
                #pragma unroll
                for (int j = 0; j < 2; j++)
                    wmma::mma_sync(acc[i][j], af[i], bf[j], acc[i][j]);
        }

        #pragma unroll
        for (int i = 0; i < 2; i++)
            #pragma unroll
            for (int j = 0; j < 2; j++)
                wmma::store_matrix_sync(sS + (wm2 * 32 + i * 16) * SC_LD + wn2 * 32 + j * 16,
                                        acc[i][j], SC_LD, wmma::mem_row_major);
        __syncthreads();

        // Warp-parallel causal softmax: each warp handles 8 rows; P in place.
        #pragma unroll 1
        for (int rr = 0; rr < 8; rr++) {
            const int t = warp * 8 + rr;
            float4 v4 = reinterpret_cast<float4*>(sS + t * SC_LD)[lane];
            const int c0 = lane * 4;

            float m = -1e30f;
            if (c0 + 0 <= t) m = fmaxf(m, v4.x);
            if (c0 + 1 <= t) m = fmaxf(m, v4.y);
            if (c0 + 2 <= t) m = fmaxf(m, v4.z);
            if (c0 + 3 <= t) m = fmaxf(m, v4.w);
            #pragma unroll
            for (int off = 16; off > 0; off >>= 1)
                m = fmaxf(m, __shfl_xor_sync(0xffffffffu, m, off));

            float e0 = (c0 + 0 <= t) ? __expf(v4.x - m) : 0.0f;
            float e1 = (c0 + 1 <= t) ? __expf(v4.y - m) : 0.0f;
            float e2 = (c0 + 2 <= t) ? __expf(v4.z - m) : 0.0f;
            float e3 = (c0 + 3 <= t) ? __expf(v4.w - m) : 0.0f;
            float s = e0 + e1 + e2 + e3;
            #pragma unroll
            for (int off = 16; off > 0; off >>= 1)
                s += __shfl_xor_sync(0xffffffffu, s, off);

            // shfl reductions converge the warp: all loads of this row done
            // before any lane stores (in-place overwrite safe).
            float inv = 1.0f / s;
            __half2* prow = reinterpret_cast<__half2*>(sp + t * SP_LD);
            prow[lane * 2 + 0] = __floats2half2_rn(e0 * inv, e1 * inv);
            prow[lane * 2 + 1] = __floats2half2_rn(e2 * inv, e3 * inv);
        }
        __syncthreads();

        // O = P @ v -> gmem
        #pragma unroll
        for (int i = 0; i < 2; i++)
            #pragma unroll
            for (int j = 0; j < 2; j++)
                wmma::fill_fragment(acc[i][j], 0.0f);

        #pragma unroll
        for (int kk = 0; kk < TT; kk += 16) {
            wmma::fragment<wmma::matrix_a, 16, 16, 16, __half, wmma::row_major> af[2];
            wmma::fragment<wmma::matrix_b, 16, 16, 16, __half, wmma::row_major> bf[2];
            #pragma unroll
            for (int i = 0; i < 2; i++)
                wmma::load_matrix_sync(af[i], sp + (wm2 * 32 + i * 16) * SP_LD + kk, SP_LD);
            #pragma unroll
            for (int j = 0; j < 2; j++)
                wmma::load_matrix_sync(bf[j], sv + kk * QK_LD + wn2 * 32 + j * 16, QK_LD);
            #pragma unroll
            for (int i = 0; i < 2; i++)
                #pragma unroll
                for (int j = 0; j < 2; j++)
                    wmma::mma_sync(acc[i][j], af[i], bf[j], acc[i][j]);
        }

        float* ob = out + (size_t)b * TT * HS;
        #pragma unroll
        for (int i = 0; i < 2; i++)
            #pragma unroll
            for (int j = 0; j < 2; j++)
                wmma::store_matrix_sync(ob + (wm2 * 32 + i * 16) * HS + wn2 * 32 + j * 16,
                                        acc[i][j], HS, wmma::mem_row_major);
    }
}

// ---------------------------------------------------------------------------
extern "C" void kernel_launch(void* const* d_in, const int* in_sizes, int n_in,
                              void* d_out, int out_size)
{
    const float* x  = (const float*)d_in[0];
    const float* Wq = (const float*)d_in[1];
    const float* Wk = (const float*)d_in[2];
    const float* Wv = (const float*)d_in[3];
    float* out = (float*)d_out;

    cudaFuncSetAttribute(fused_head_kernel, cudaFuncAttributeMaxDynamicSharedMemorySize, FUSED_SMEM);

    conv_wh_kernel<<<192, 256>>>(Wq, Wk, Wv);
    fused_head_kernel<<<NB, 512, FUSED_SMEM>>>(x, out);
}

// round 16
// speedup vs baseline: 1.0739x; 1.0739x over previous
#include <cuda_runtime.h>
#include <cuda_fp16.h>
#include <cstdint>
#include <mma.h>

using namespace nvcuda;

#define NEMBD 1024
#define TT 128
#define HS 128
#define NB 256

// W pre-converted to fp16 (device global; no allocations allowed).
__device__ __half g_wh[(size_t)3 * NEMBD * HS];    // Wq|Wk|Wv, RN fp16

// ---------------------------------------------------------------------------
// Pre-pass: RN-round W fp32 -> fp16.
// ---------------------------------------------------------------------------
__global__ void conv_wh_kernel(const float* __restrict__ wq,
                               const float* __restrict__ wk,
                               const float* __restrict__ wv)
{
    const int n4 = NEMBD * HS / 4;
    int stride = gridDim.x * blockDim.x;
    for (int i = blockIdx.x * blockDim.x + threadIdx.x; i < 3 * n4; i += stride) {
        int w = i / n4, j = i % n4;
        const float* src = (w == 0) ? wq : (w == 1) ? wk : wv;
        float4 v = reinterpret_cast<const float4*>(src)[j];
        reinterpret_cast<__half2*>(g_wh)[i * 2 + 0] = __floats2half2_rn(v.x, v.y);
        reinterpret_cast<__half2*>(g_wh)[i * 2 + 1] = __floats2half2_rn(v.z, v.w);
    }
}

// ---------------------------------------------------------------------------
// Fused kernel (R14 structure, best measured): per-batch QKV GEMM (fp16
// HMMA) + RoPE + causal attention. 256 CTAs, 512 threads / 16 warps.
// Change vs R14: q/k epilogue applies RoPE IN REGISTERS using the sm_80
// accumulator fragment layout (thread holds adjacent col pairs), then
// stores half fragments directly to the sq/sk tiles. No fp32 staging, no
// per-section barriers (one sync before phase 2).
// ---------------------------------------------------------------------------
static constexpr int A32_LD = 36;                      // floats (32 + 4 pad)
static constexpr int AH_LD  = 40;                      // halves (32 + 8 pad)
static constexpr int BH_LD  = 392;                     // halves (384 + 8 pad)
static constexpr int A32_B  = 128 * A32_LD * 4;        // 18432 B
static constexpr int AH_B   = 128 * AH_LD * 2;         // 10240 B
static constexpr int BH_B   = 32 * BH_LD * 2;          // 25088 B
static constexpr int STG_B  = A32_B + AH_B + BH_B;     // 53760 B
static constexpr int NBUF   = 4;
static constexpr int FUSED_SMEM = NBUF * STG_B;        // 215040 B

// Post-mainloop layout (within the same allocation):
static constexpr int SC_LD   = 132;                    // S floats
static constexpr int SC_B    = 128 * SC_LD * 4;        // 67584 B
static constexpr int QK_LD   = 136;                    // fp16 tile ld (halves)
static constexpr int TILE_B  = 128 * QK_LD * 2;        // 34816 B
static constexpr int SQ_OFF  = SC_B;                   // 67584
static constexpr int SK_OFF  = SQ_OFF + TILE_B;        // 102400
static constexpr int SV_OFF  = SK_OFF + TILE_B;        // 137216  (end 172032)
static constexpr int SP_LD   = 264;                    // P halves ld

__device__ __forceinline__ void cp_async16(void* sptr, const void* gptr)
{
    uint32_t sa = (uint32_t)__cvta_generic_to_shared(sptr);
    asm volatile("cp.async.cg.shared.global [%0], [%1], 16;\n" :: "r"(sa), "l"(gptr));
}

__global__ void __launch_bounds__(512)
fused_head_kernel(const float* __restrict__ x, float* __restrict__ out)
{
    extern __shared__ char smemc[];
    const int b    = blockIdx.x;          // batch
    const int tid  = threadIdx.x;
    const int warp = tid >> 5;
    const int lane = tid & 31;
    const int wm   = warp >> 2;           // 0..3 -> 32-row band
    const int wn   = warp & 3;            // 0..3 -> 96-col band (phase 1)

    const float* xbase = x + (size_t)b * TT * NEMBD;

    // A chunk ownership (load AND convert): row cr, 8-float segment cc0.
    const int cr  = tid >> 2;
    const int cc0 = (tid & 3) * 8;

    // ============================ Phase 1: QKV GEMM ========================
    {
        wmma::fragment<wmma::accumulator, 16, 16, 16, float> acc[2][6];
        #pragma unroll
        for (int i = 0; i < 2; i++)
            #pragma unroll
            for (int j = 0; j < 6; j++)
                wmma::fill_fragment(acc[i][j], 0.0f);

        auto load_stage = [&](int stage) {      // stage 0..31
            char* st = smemc + (stage & 3) * STG_B;
            float*  As32 = reinterpret_cast<float*>(st);
            __half* Bs   = reinterpret_cast<__half*>(st + A32_B + AH_B);
            int k0 = stage * 32;
            // A: each thread loads ITS OWN 8 floats (2 x 16B).
            cp_async16(As32 + cr * A32_LD + cc0,
                       xbase + (size_t)cr * NEMBD + k0 + cc0);
            cp_async16(As32 + cr * A32_LD + cc0 + 4,
                       xbase + (size_t)cr * NEMBD + k0 + cc0 + 4);
            // B: 1536 8-half ops, 3/thread
            #pragma unroll
            for (int j = 0; j < 3; j++) {
                int idx = tid + j * 512;
                int r = idx / 48, c = idx % 48;
                int w = c >> 4;
                int cc = (c & 15) * 8;
                cp_async16(Bs + r * BH_LD + c * 8,
                           g_wh + (size_t)w * NEMBD * HS + (size_t)(k0 + r) * HS + cc);
            }
        };

        load_stage(0); asm volatile("cp.async.commit_group;\n");
        load_stage(1); asm volatile("cp.async.commit_group;\n");
        load_stage(2); asm volatile("cp.async.commit_group;\n");

        for (int it = 0; it < 32; ++it) {
            asm volatile("cp.async.wait_group 2;\n");

            char* st = smemc + (it & 3) * STG_B;
            float*  As32 = reinterpret_cast<float*>(st);
            __half* Ah   = reinterpret_cast<__half*>(st + A32_B);
            __half* Bs   = reinterpret_cast<__half*>(st + A32_B + AH_B);

            // Convert OWN chunk (visible after wait_group): 2xLDS.128 ->
            // 1xSTS.128. No barrier needed before this.
            {
                const float4* src = reinterpret_cast<const float4*>(As32 + cr * A32_LD + cc0);
                float4 f0 = src[0], f1 = src[1];
                uint4 o;
                reinterpret_cast<__half2*>(&o)[0] = __floats2half2_rn(f0.x, f0.y);
                reinterpret_cast<__half2*>(&o)[1] = __floats2half2_rn(f0.z, f0.w);
                reinterpret_cast<__half2*>(&o)[2] = __floats2half2_rn(f1.x, f1.y);
                reinterpret_cast<__half2*>(&o)[3] = __floats2half2_rn(f1.z, f1.w);
                *reinterpret_cast<uint4*>(Ah + cr * AH_LD + cc0) = o;
            }
            __syncthreads();     // publish Ah(it) + B(it); also fences buffer reuse

            #pragma unroll
            for (int kk = 0; kk < 32; kk += 16) {
                wmma::fragment<wmma::matrix_a, 16, 16, 16, __half, wmma::row_major> af[2];
                wmma::fragment<wmma::matrix_b, 16, 16, 16, __half, wmma::row_major> bf[6];
                #pragma unroll
                for (int i = 0; i < 2; i++)
                    wmma::load_matrix_sync(af[i], Ah + (wm * 32 + i * 16) * AH_LD + kk, AH_LD);
                #pragma unroll
                for (int j = 0; j < 6; j++)
                    wmma::load_matrix_sync(bf[j], Bs + kk * BH_LD + wn * 96 + j * 16, BH_LD);
                #pragma unroll
                for (int i = 0; i < 2; i++)
                    #pragma unroll
                    for (int j = 0; j < 6; j++)
                        wmma::mma_sync(acc[i][j], af[i], bf[j], acc[i][j]);
            }

            if (it + 3 < 32) load_stage(it + 3);
            asm volatile("cp.async.commit_group;\n");
        }

        asm volatile("cp.async.wait_group 0;\n");
        __syncthreads();          // mainloop fully drained; smem reusable

        // ---- Epilogue: RoPE in registers, direct half-fragment stores -----
        // fp32 acc fragment layout (sm_80 m16n16k16): element e of thread
        // lane maps to row = frag_row + (lane>>2) + 8*((e>>1)&1),
        //              col = frag_col + (lane&3)*2 + 8*(e>>2) + (e&1).
        // Pairs (x[2t], x[2t+1]) are adjacent columns -> RoPE is thread-local.
        {
            __half* sq = reinterpret_cast<__half*>(smemc + SQ_OFF);
            __half* sk = reinterpret_cast<__half*>(smemc + SK_OFF);
            __half* sv = reinterpret_cast<__half*>(smemc + SV_OFF);
            const float nlt = -logf(10000.0f) * (2.0f / 128.0f);
            const int r0 = lane >> 2;
            const int c0 = (lane & 3) * 2;

            #pragma unroll
            for (int i = 0; i < 2; i++)
                #pragma unroll
                for (int j = 0; j < 6; j++) {
                    int colg = wn * 96 + j * 16;     // fragment col base (16-wide,
                    int w = colg >> 7;               //   never straddles a section)
                    int rowbase = wm * 32 + i * 16;
                    wmma::fragment<wmma::accumulator, 16, 16, 16, __half> hf;
                    if (w == 2) {
                        #pragma unroll
                        for (int e = 0; e < 8; e++)
                            hf.x[e] = __float2half_rn(acc[i][j].x[e]);
                        wmma::store_matrix_sync(sv + rowbase * QK_LD + (colg - 256),
                                                hf, QK_LD, wmma::mem_row_major);
                    } else {
                        const float qs = (w == 0) ? 0.08838834764831845f : 1.0f;
                        #pragma unroll
                        for (int e = 0; e < 8; e += 2) {
                            int row  = rowbase + r0 + (((e >> 1) & 1) ? 8 : 0);
                            int colp = (colg & 127) + c0 + ((e >> 2) ? 8 : 0);
                            int p = colp >> 1;
                            float inv_freq = __expf(nlt * (float)p);
                            float ang = (float)row * inv_freq;
                            float s, c;
                            sincosf(ang, &s, &c);
                            float crv = acc[i][j].x[e];
                            float civ = acc[i][j].x[e + 1];
                            hf.x[e]     = __float2half_rn((crv * c - civ * s) * qs);
                            hf.x[e + 1] = __float2half_rn((crv * s + civ * c) * qs);
                        }
                        __half* tile = (w == 0) ? sq : sk;
                        wmma::store_matrix_sync(tile + rowbase * QK_LD + (colg & 127),
                                                hf, QK_LD, wmma::mem_row_major);
                    }
                }
            __syncthreads();      // all tiles written before phase 2
        }
    }

    // ============================ Phase 2: attention ========================
    {
        __half* sq = reinterpret_cast<__half*>(smemc + SQ_OFF);
        __half* sk = reinterpret_cast<__half*>(smemc + SK_OFF);
        __half* sv = reinterpret_cast<__half*>(smemc + SV_OFF);
        float*  sS = reinterpret_cast<float*>(smemc);        // [128][132]
        __half* sp = reinterpret_cast<__half*>(smemc);       // P view, ld 264

        const int wm2 = warp >> 2;   // 0..3 -> 32-row band
        const int wn2 = warp & 3;    // 0..3 -> 32-col band

        // S = q @ k^T
        wmma::fragment<wmma::accumulator, 16, 16, 16, float> acc[2][2];
        #pragma unroll
        for (int i = 0; i < 2; i++)
            #pragma unroll
            for (int j = 0; j < 2; j++)
                wmma::fill_fragment(acc[i][j], 0.0f);

        #pragma unroll
        for (int kk = 0; kk < HS; kk += 16) {
            wmma::fragment<wmma::matrix_a, 16, 16, 16, __half, wmma::row_major> af[2];
            wmma::fragment<wmma::matrix_b, 16, 16, 16, __half, wmma::col_major> bf[2];
            #pragma unroll
            for (int i = 0; i < 2; i++)
                wmma::load_matrix_sync(af[i], sq + (wm2 * 32 + i * 16) * QK_LD + kk, QK_LD);
            #pragma unroll
            for (int j = 0; j < 2; j++)
                wmma::load_matrix_sync(bf[j], sk + (wn2 * 32 + j * 16) * QK_LD + kk, QK_LD);
            #pragma unroll
            for (int i = 0; i < 2; i++)
                #pragma unroll
                for (int j = 0; j < 2; j++)
                    wmma::mma_sync(acc[i][j], af[i], bf[j], acc[i][j]);
        }

        #pragma unroll
        for (int i = 0; i < 2; i++)
            #pragma unroll
            for (int j = 0; j < 2; j++)
                wmma::store_matrix_sync(sS + (wm2 * 32 + i * 16) * SC_LD + wn2 * 32 + j * 16,
                                        acc[i][j], SC_LD, wmma::mem_row_major);
        __syncthreads();

        // Warp-parallel causal softmax: each warp handles 8 rows; P in place.
        #pragma unroll 1
        for (int rr = 0; rr < 8; rr++) {
            const int t = warp * 8 + rr;
            float4 v4 = reinterpret_cast<float4*>(sS + t * SC_LD)[lane];
            const int c0s = lane * 4;

            float m = -1e30f;
            if (c0s + 0 <= t) m = fmaxf(m, v4.x);
            if (c0s + 1 <= t) m = fmaxf(m, v4.y);
            if (c0s + 2 <= t) m = fmaxf(m, v4.z);
            if (c0s + 3 <= t) m = fmaxf(m, v4.w);
            #pragma unroll
            for (int off = 16; off > 0; off >>= 1)
                m = fmaxf(m, __shfl_xor_sync(0xffffffffu, m, off));

            float e0 = (c0s + 0 <= t) ? __expf(v4.x - m) : 0.0f;
            float e1 = (c0s + 1 <= t) ? __expf(v4.y - m) : 0.0f;
            float e2 = (c0s + 2 <= t) ? __expf(v4.z - m) : 0.0f;
            float e3 = (c0s + 3 <= t) ? __expf(v4.w - m) : 0.0f;
            float s = e0 + e1 + e2 + e3;
            #pragma unroll
            for (int off = 16; off > 0; off >>= 1)
                s += __shfl_xor_sync(0xffffffffu, s, off);

            // shfl reductions converge the warp: all loads of this row done
            // before any lane stores (in-place overwrite safe).
            float inv = 1.0f / s;
            __half2* prow = reinterpret_cast<__half2*>(sp + t * SP_LD);
            prow[lane * 2 + 0] = __floats2half2_rn(e0 * inv, e1 * inv);
            prow[lane * 2 + 1] = __floats2half2_rn(e2 * inv, e3 * inv);
        }
        __syncthreads();

        // O = P @ v -> gmem
        #pragma unroll
        for (int i = 0; i < 2; i++)
            #pragma unroll
            for (int j = 0; j < 2; j++)
                wmma::fill_fragment(acc[i][j], 0.0f);

        #pragma unroll
        for (int kk = 0; kk < TT; kk += 16) {
            wmma::fragment<wmma::matrix_a, 16, 16, 16, __half, wmma::row_major> af[2];
            wmma::fragment<wmma::matrix_b, 16, 16, 16, __half, wmma::row_major> bf[2];
            #pragma unroll
            for (int i = 0; i < 2; i++)
                wmma::load_matrix_sync(af[i], sp + (wm2 * 32 + i * 16) * SP_LD + kk, SP_LD);
            #pragma unroll
            for (int j = 0; j < 2; j++)
                wmma::load_matrix_sync(bf[j], sv + kk * QK_LD + wn2 * 32 + j * 16, QK_LD);
            #pragma unroll
            for (int i = 0; i < 2; i++)
                #pragma unroll
                for (int j = 0; j < 2; j++)
                    wmma::mma_sync(acc[i][j], af[i], bf[j], acc[i][j]);
        }

        float* ob = out + (size_t)b * TT * HS;
        #pragma unroll
        for (int i = 0; i < 2; i++)
            #pragma unroll
            for (int j = 0; j < 2; j++)
                wmma::store_matrix_sync(ob + (wm2 * 32 + i * 16) * HS + wn2 * 32 + j * 16,
                                        acc[i][j], HS, wmma::mem_row_major);
    }
}

// ---------------------------------------------------------------------------
extern "C" void kernel_launch(void* const* d_in, const int* in_sizes, int n_in,
                              void* d_out, int out_size)
{
    const float* x  = (const float*)d_in[0];
    const float* Wq = (const float*)d_in[1];
    const float* Wk = (const float*)d_in[2];
    const float* Wv = (const float*)d_in[3];
    float* out = (float*)d_out;

    cudaFuncSetAttribute(fused_head_kernel, cudaFuncAttributeMaxDynamicSharedMemorySize, FUSED_SMEM);

    conv_wh_kernel<<<192, 256>>>(Wq, Wk, Wv);
    fused_head_kernel<<<NB, 512, FUSED_SMEM>>>(x, out);
}